// round 11
// baseline (speedup 1.0000x reference)
#include <cuda_runtime.h>
#include <math.h>

#define Bb   2
#define Nn   1024
#define DIMM 1024
#define Hh   8
#define DHh  64
#define DIi  512
#define BN   (Bb*Nn)
#define NC   16          // chunks per (b,h)
#define CS   64          // chunk size

static __device__ __constant__ float EPSf = 1.1920929e-07f;

// ---------------- scratch ----------------
__device__ float g_xa[BN*DIMM];
__device__ float g_qp[BN*DIi];
__device__ float g_kp[BN*DIi];
__device__ float g_vp[BN*DIi];
__device__ float g_qp2[BN*DIi];
__device__ float g_kp2[BN*DIi];
__device__ float g_vp2[BN*DIi];
__device__ float g_y [BN*DIi];
__device__ float g_ga[BN*24];
__device__ float g_gz[256*4096];
__device__ float g_gs[256*4096];
__device__ float g_sc[256*128];
__device__ float g_sc2[256*4];

// ---------------- tf32 helpers ----------------
__device__ __forceinline__ unsigned f2tf(float f) {
    unsigned r; asm("cvt.rna.tf32.f32 %0, %1;" : "=r"(r) : "f"(f)); return r;
}
__device__ __forceinline__ uint4 tf4(float4 v) {
    return make_uint4(f2tf(v.x), f2tf(v.y), f2tf(v.z), f2tf(v.w));
}
__device__ __forceinline__ void mma_tf32(float* c, const unsigned* a, const unsigned* b) {
    asm volatile(
        "mma.sync.aligned.m16n8k8.row.col.f32.tf32.tf32.f32 "
        "{%0,%1,%2,%3}, {%4,%5,%6,%7}, {%8,%9}, {%0,%1,%2,%3};"
        : "+f"(c[0]), "+f"(c[1]), "+f"(c[2]), "+f"(c[3])
        : "r"(a[0]), "r"(a[1]), "r"(a[2]), "r"(a[3]), "r"(b[0]), "r"(b[1]));
}

// ---------------- 1. RMSNorm ----------------
__global__ void k_rmsnorm(const float* __restrict__ x, const float* __restrict__ w) {
    int row = blockIdx.x;
    int tid = threadIdx.x;
    const float4* xr = (const float4*)(x + (size_t)row * DIMM);
    float4 xv = xr[tid];
    float ss = xv.x*xv.x + xv.y*xv.y + xv.z*xv.z + xv.w*xv.w;
    #pragma unroll
    for (int o = 16; o > 0; o >>= 1) ss += __shfl_xor_sync(0xffffffffu, ss, o);
    __shared__ float sred[8];
    if ((tid & 31) == 0) sred[tid >> 5] = ss;
    __syncthreads();
    float tot = 0.f;
    #pragma unroll
    for (int i = 0; i < 8; i++) tot += sred[i];
    float inv = rsqrtf(tot * (1.0f / DIMM) + EPSf);
    float4 wv = ((const float4*)w)[tid];
    float4 o;
    o.x = xv.x * inv * wv.x; o.y = xv.y * inv * wv.y;
    o.z = xv.z * inv * wv.z; o.w = xv.w * inv * wv.w;
    ((float4*)g_xa)[(size_t)row * (DIMM/4) + tid] = o;
}

// ---------------- 2. tf32 GEMM core: double-buffered smem, split-K --------
template<bool FC, int MI, int WCN>
__device__ __forceinline__ void gemm_tc(const float* __restrict__ A,
                                        const float* __restrict__ Bm,
                                        float* __restrict__ C,
                                        int Nc, int Kc, int koff,
                                        const float* __restrict__ cw) {
    extern __shared__ unsigned smem[];
    unsigned* As = smem;                  // [2][4*520]
    unsigned* Bs = smem + 2*2080;         // [2][WCN*8*128]
    const int BSW = WCN*8*128;
    int tid = threadIdx.x;
    int lane = tid & 31, wid = tid >> 5;
    int wr = wid / WCN, wc = wid % WCN;
    int gid = lane >> 2, tig = lane & 3;
    int row0 = blockIdx.y * 128, col0 = blockIdx.x * (WCN*64);

    int ar = tid >> 1;
    int kqb = (tid & 1) * 2;
    int bk = lane >> 1, bq = lane & 1;

    int m = row0 + ar;
    int tloc = 0, b0 = 0;
    if (FC) { b0 = m & ~(Nn - 1); tloc = m - b0; }

    float acc[MI][8][4];
    #pragma unroll
    for (int i = 0; i < MI; i++)
        #pragma unroll
        for (int j = 0; j < 8; j++)
            #pragma unroll
            for (int q = 0; q < 4; q++) acc[i][j][q] = 0.f;

    float4 ra[2], rb[WCN];
    const float4* A4 = (const float4*)A;
    const float4* B4 = (const float4*)Bm;
    const float4* XA4 = (const float4*)g_xa;
    const float4* CW4 = (const float4*)cw;

    #define PREFETCH(kn)                                                        \
    {                                                                           \
        _Pragma("unroll")                                                       \
        for (int p = 0; p < 2; p++) {                                           \
            int kq = kqb + p;                                                   \
            if (!FC) {                                                          \
                ra[p] = A4[(size_t)m * (Kc >> 2) + (((kn)+koff) >> 2) + kq];    \
            } else {                                                            \
                int kb = koff + (kn) + kq * 4;                                  \
                float we[4][4];                                                 \
                _Pragma("unroll")                                               \
                for (int e = 0; e < 4; e++) *(float4*)we[e] = CW4[kb + e];      \
                float4 r = make_float4(0.f, 0.f, 0.f, 0.f);                     \
                _Pragma("unroll")                                               \
                for (int j = 0; j < 4; j++) {                                   \
                    int tl = tloc + j - 2;                                      \
                    if ((unsigned)tl < (unsigned)Nn) {                          \
                        float4 xv = XA4[(size_t)(b0 + tl) * (DIMM >> 2) + (kb >> 2)]; \
                        r.x += xv.x * we[0][j]; r.y += xv.y * we[1][j];         \
                        r.z += xv.z * we[2][j]; r.w += xv.w * we[3][j];         \
                    }                                                           \
                }                                                               \
                ra[p] = r;                                                      \
            }                                                                   \
        }                                                                       \
        _Pragma("unroll")                                                       \
        for (int p = 0; p < WCN; p++) {                                         \
            int nt = wid + p * 8;                                               \
            rb[p] = B4[(size_t)(koff + (kn) + bk) * (Nc >> 2) + (col0 >> 2) + nt * 2 + bq]; \
        }                                                                       \
    }

    #define STORE(buf)                                                          \
    {                                                                           \
        unsigned* Aw = As + (buf)*2080;                                         \
        unsigned* Bw = Bs + (buf)*BSW;                                          \
        _Pragma("unroll")                                                       \
        for (int p = 0; p < 2; p++)                                             \
            *(uint4*)&Aw[(kqb+p)*520 + ar*4] = tf4(ra[p]);                      \
        _Pragma("unroll")                                                       \
        for (int p = 0; p < WCN; p++) {                                         \
            int nt = wid + p * 8;                                               \
            *(uint4*)&Bw[nt*128 + bk*8 + bq*4] = tf4(rb[p]);                    \
        }                                                                       \
    }

    PREFETCH(0)
    STORE(0)
    __syncthreads();

    for (int k0 = 0; k0 < Kc; k0 += 16) {
        int cur = (k0 >> 4) & 1;
        bool more = (k0 + 16 < Kc);
        if (more) PREFETCH(k0 + 16)
        const unsigned* Abuf = As + cur*2080;
        const unsigned* Bbuf = Bs + cur*BSW;
        #pragma unroll
        for (int c = 0; c < 2; c++) {
            unsigned a[MI][4];
            const unsigned* s0 = Abuf + (c*2)*520;
            const unsigned* s1 = Abuf + (c*2+1)*520;
            #pragma unroll
            for (int mi = 0; mi < MI; mi++) {
                int m0 = (wr*MI + mi) * 16;
                a[mi][0] = s0[(m0+gid)*4 + tig];
                a[mi][1] = s0[(m0+gid+8)*4 + tig];
                a[mi][2] = s1[(m0+gid)*4 + tig];
                a[mi][3] = s1[(m0+gid+8)*4 + tig];
            }
            #pragma unroll
            for (int ni = 0; ni < 8; ni++) {
                int nt = wc*8 + ni;
                unsigned b[2];
                b[0] = Bbuf[nt*128 + (c*8+tig)*8 + gid];
                b[1] = Bbuf[nt*128 + (c*8+tig+4)*8 + gid];
                #pragma unroll
                for (int mi = 0; mi < MI; mi++) mma_tf32(acc[mi][ni], a[mi], b);
            }
        }
        if (more) {
            STORE(cur ^ 1)
            __syncthreads();
        }
    }
    #undef PREFETCH
    #undef STORE

    #pragma unroll
    for (int mi = 0; mi < MI; mi++) {
        #pragma unroll
        for (int ni = 0; ni < 8; ni++) {
            int row = row0 + (wr*MI + mi)*16 + gid;
            int col = col0 + (wc*8 + ni)*8 + tig*2;
            *(float2*)(C + (size_t)row * Nc + col) =
                make_float2(acc[mi][ni][0], acc[mi][ni][1]);
            *(float2*)(C + (size_t)(row+8) * Nc + col) =
                make_float2(acc[mi][ni][2], acc[mi][ni][3]);
        }
    }
}

// z = mat*2 + khalf
__global__ __launch_bounds__(256, 1)
void k_gemm3(const float* __restrict__ B0, const float* __restrict__ B1,
             const float* __restrict__ B2,
             const float* __restrict__ cw0, const float* __restrict__ cw1,
             const float* __restrict__ cw2,
             float* __restrict__ C0a, float* __restrict__ C1a,
             float* __restrict__ C2a,
             float* __restrict__ C0b, float* __restrict__ C1b,
             float* __restrict__ C2b) {
    int mat = blockIdx.z >> 1, half = blockIdx.z & 1;
    const float* Bm = (mat == 0) ? B0 : ((mat == 1) ? B1 : B2);
    const float* cw = (mat == 0) ? cw0 : ((mat == 1) ? cw1 : cw2);
    float* C;
    if (half == 0) C = (mat == 0) ? C0a : ((mat == 1) ? C1a : C2a);
    else           C = (mat == 0) ? C0b : ((mat == 1) ? C1b : C2b);
    gemm_tc<true, 4, 4>(nullptr, Bm, C, DIi, DIMM/2, half*(DIMM/2), cw);
}

__global__ __launch_bounds__(256, 1)
void k_gemm1(const float* __restrict__ A, const float* __restrict__ Bm,
             float* __restrict__ C, int Nc, int Kc) {
    gemm_tc<false, 2, 2>(A, Bm, C, Nc, Kc, 0, nullptr);
}

// ---------------- 3. gate projections, split-K, 64-row tiles --------------
__global__ void k_gates2(const float* __restrict__ lw, const float* __restrict__ dw,
                         const float* __restrict__ mw) {
    __shared__ float As[64][20];
    __shared__ float Ws[16][24];
    int tid = threadIdx.x;
    int hh = tid & 7, ty = tid >> 3;
    int row0 = blockIdx.x * 64;
    int kbase = blockIdx.y * 128;
    float acc[2][3] = {};
    for (int k0 = kbase; k0 < kbase + 128; k0 += 16) {
        {
            int mm = tid >> 2, kq = (tid & 3) * 4;
            float4 v = *(const float4*)(g_xa + (size_t)(row0+mm)*DIMM + k0 + kq);
            As[mm][kq+0]=v.x; As[mm][kq+1]=v.y; As[mm][kq+2]=v.z; As[mm][kq+3]=v.w;
        }
        if (tid < 128) {
            int kk = tid >> 3, h2 = tid & 7;
            Ws[kk][h2]    = lw[(k0+kk)*Hh + h2];
            Ws[kk][8+h2]  = dw[(k0+kk)*Hh + h2];
            Ws[kk][16+h2] = mw[(k0+kk)*Hh + h2];
        }
        __syncthreads();
        #pragma unroll
        for (int kk = 0; kk < 16; kk++) {
            float a0 = As[ty*2][kk], a1 = As[ty*2+1][kk];
            float w0 = Ws[kk][hh], w1 = Ws[kk][8+hh], w2 = Ws[kk][16+hh];
            acc[0][0] += a0*w0; acc[0][1] += a0*w1; acc[0][2] += a0*w2;
            acc[1][0] += a1*w0; acc[1][1] += a1*w1; acc[1][2] += a1*w2;
        }
        __syncthreads();
    }
    #pragma unroll
    for (int i = 0; i < 2; i++) {
        int row = row0 + ty*2 + i;
        atomicAdd(&g_ga[row*24 + hh],      acc[i][0]);
        atomicAdd(&g_ga[row*24 + 8 + hh],  acc[i][1]);
        atomicAdd(&g_ga[row*24 + 16 + hh], acc[i][2]);
    }
}

// ---------------- 4a. chunk kernel A: tf32 mma on all four 64^3 GEMMs -----
__global__ __launch_bounds__(256, 1)
void k_chunkA(const float* __restrict__ lb, const float* __restrict__ db,
              const float* __restrict__ mb,
              const float* __restrict__ gq, const float* __restrict__ gk) {
    extern __shared__ float sm[];
    float* sq  = sm;            // 64x65 (q, then T)
    float* sk  = sm + 4160;
    float* sv  = sm + 8320;
    float* sE  = sm + 12480;
    float* slr = sm + 16640;
    float* sde = sm + 16704;
    float* smo = sm + 16768;
    float* sAe = sm + 16832;
    float* sEe = sm + 16896;
    float* ssc = sm + 16960;
    float* ssc2= sm + 17088;

    int tid = threadIdx.x;
    int lane = tid & 31, wid = tid >> 5;
    int gid = lane >> 2, t4 = lane & 3;
    int wm = wid & 3, wn = wid >> 2;     // row group (16), col half (32)
    int cc = blockIdx.x;
    int bh = cc >> 4, c = cc & 15;
    int b = bh >> 3, h = bh & 7;
    int t0 = c * CS;
    const size_t base = (size_t)b * Nn * DIi + h * DHh;

    // load q,k,v chunk (sum of split-K halves) into padded smem
    {
        int f4 = tid & 15, r0 = tid >> 4;
        #pragma unroll
        for (int rr = 0; rr < 4; rr++) {
            int row = rr*16 + r0;
            size_t g = base + (size_t)(t0+row)*DIi + f4*4;
            float4 q1 = *(const float4*)(g_qp + g);
            float4 q2 = *(const float4*)(g_qp2 + g);
            float4 k1 = *(const float4*)(g_kp + g);
            float4 k2 = *(const float4*)(g_kp2 + g);
            float4 v1 = *(const float4*)(g_vp + g);
            float4 v2 = *(const float4*)(g_vp2 + g);
            int so = row*65 + f4*4;
            sq[so]=q1.x+q2.x; sq[so+1]=q1.y+q2.y; sq[so+2]=q1.z+q2.z; sq[so+3]=q1.w+q2.w;
            sk[so]=k1.x+k2.x; sk[so+1]=k1.y+k2.y; sk[so+2]=k1.z+k2.z; sk[so+3]=k1.w+k2.w;
            sv[so]=v1.x+v2.x; sv[so+1]=v1.y+v2.y; sv[so+2]=v1.z+v2.z; sv[so+3]=v1.w+v2.w;
        }
    }
    // gates (sigmoid)
    if (tid < 192) {
        int i = tid / 3, gi = tid - i*3;
        const float* bb = (gi==0) ? lb : ((gi==1) ? db : mb);
        float raw = g_ga[(size_t)(b*Nn + t0 + i)*24 + gi*8 + h] + bb[h];
        float v = 1.f/(1.f+__expf(-raw));
        ((gi==0) ? slr : ((gi==1) ? sde : smo))[i] = v;
    }
    __syncthreads();

    // fused per-head RMSNorm of q,k; write normalized q back for chunkB
    {
        int row = tid >> 2, seg = (tid & 3) * 16;
        float ssq = 0.f, ssk = 0.f;
        #pragma unroll
        for (int j = 0; j < 16; j++) {
            float a = sq[row*65 + seg + j]; ssq += a*a;
            float e = sk[row*65 + seg + j]; ssk += e*e;
        }
        ssq += __shfl_xor_sync(0xffffffffu, ssq, 1);
        ssq += __shfl_xor_sync(0xffffffffu, ssq, 2);
        ssk += __shfl_xor_sync(0xffffffffu, ssk, 1);
        ssk += __shfl_xor_sync(0xffffffffu, ssk, 2);
        float invq = 1.f / fmaxf(sqrtf(ssq) * 0.125f, 1e-8f);
        float invk = 1.f / fmaxf(sqrtf(ssk) * 0.125f, 1e-8f);
        float qb[16];
        #pragma unroll
        for (int j = 0; j < 16; j++) {
            float nq = sq[row*65 + seg + j] * invq * gq[h*DHh + seg + j];
            sq[row*65 + seg + j] = nq; qb[j] = nq;
            sk[row*65 + seg + j] = sk[row*65 + seg + j] * invk * gk[h*DHh + seg + j];
        }
        #pragma unroll
        for (int j = 0; j < 4; j++)
            *(float4*)(g_qp + base + (size_t)(t0+row)*DIi + seg + j*4) =
                make_float4(qb[j*4], qb[j*4+1], qb[j*4+2], qb[j*4+3]);
    }
    // coefficient recurrences (threads 0..63)
    if (tid < 64) {
        int u = tid;
        float A_=0.f, E_=0.f, Amul=1.f, Dmul=1.f, F=0.f;
        for (int i = 0; i < 64; i++) {
            sE[i*65 + u] = E_;
            if (u == i) { ssc[i*2] = Dmul; ssc[i*2+1] = F; }
            float ai = smo[i], di = sde[i], li = slr[i];
            A_ = ai * A_; if (u == i) A_ = 1.f;
            E_ = di * E_ + li * A_;
            Amul *= ai; F = di * F + li * Amul; Dmul *= di;
        }
        sAe[u] = A_; sEe[u] = E_;
        if (u == 0) { ssc2[0] = Amul; ssc2[1] = Dmul; ssc2[2] = F; }
    }
    __syncthreads();

    // ---- GEMM1 (mma): attn[i][u] = q_i . k_u  (warp: 16 i x 32 u) ----
    float acc1[4][4];
    #pragma unroll
    for (int ni = 0; ni < 4; ni++)
        #pragma unroll
        for (int q = 0; q < 4; q++) acc1[ni][q] = 0.f;
    #pragma unroll
    for (int p = 0; p < 8; p++) {
        int k0 = p * 8;
        unsigned a[4];
        a[0] = f2tf(sq[(wm*16+gid)*65   + k0+t4]);
        a[1] = f2tf(sq[(wm*16+gid+8)*65 + k0+t4]);
        a[2] = f2tf(sq[(wm*16+gid)*65   + k0+t4+4]);
        a[3] = f2tf(sq[(wm*16+gid+8)*65 + k0+t4+4]);
        #pragma unroll
        for (int ni = 0; ni < 4; ni++) {
            int u0 = wn*32 + ni*8;
            unsigned bb[2];
            bb[0] = f2tf(sk[(u0+gid)*65 + k0+t4]);
            bb[1] = f2tf(sk[(u0+gid)*65 + k0+t4+4]);
            mma_tf32(acc1[ni], a, bb);
        }
    }
    __syncthreads();          // all reads of sq done
    // T = attn * E-mask -> sq
    #pragma unroll
    for (int ni = 0; ni < 4; ni++) {
        int i0 = wm*16 + gid;
        int u0 = wn*32 + ni*8 + 2*t4;
        sq[i0*65 + u0]       = acc1[ni][0] * sE[i0*65 + u0];
        sq[i0*65 + u0+1]     = acc1[ni][1] * sE[i0*65 + u0+1];
        sq[(i0+8)*65 + u0]   = acc1[ni][2] * sE[(i0+8)*65 + u0];
        sq[(i0+8)*65 + u0+1] = acc1[ni][3] * sE[(i0+8)*65 + u0+1];
    }
    __syncthreads();

    // ---- GEMM2 (mma): y_intra = T @ V  (warp: 16 i x 32 r) ----
    float acc2[4][4];
    #pragma unroll
    for (int ni = 0; ni < 4; ni++)
        #pragma unroll
        for (int q = 0; q < 4; q++) acc2[ni][q] = 0.f;
    #pragma unroll
    for (int p = 0; p < 8; p++) {
        int k0 = p * 8;
        unsigned a[4];
        a[0] = f2tf(sq[(wm*16+gid)*65   + k0+t4]);
        a[1] = f2tf(sq[(wm*16+gid+8)*65 + k0+t4]);
        a[2] = f2tf(sq[(wm*16+gid)*65   + k0+t4+4]);
        a[3] = f2tf(sq[(wm*16+gid+8)*65 + k0+t4+4]);
        #pragma unroll
        for (int ni = 0; ni < 4; ni++) {
            int r0 = wn*32 + ni*8;
            unsigned bb[2];
            bb[0] = f2tf(sv[(k0+t4)*65   + r0+gid]);
            bb[1] = f2tf(sv[(k0+t4+4)*65 + r0+gid]);
            mma_tf32(acc2[ni], a, bb);
        }
    }
    #pragma unroll
    for (int ni = 0; ni < 4; ni++) {
        int i0 = wm*16 + gid;
        int r0 = wn*32 + ni*8 + 2*t4;
        *(float2*)(g_y + base + (size_t)(t0+i0)*DIi + r0) =
            make_float2(acc2[ni][0], acc2[ni][1]);
        *(float2*)(g_y + base + (size_t)(t0+i0+8)*DIi + r0) =
            make_float2(acc2[ni][2], acc2[ni][3]);
    }

    // ---- GEMM3/4 (mma): G_z = (diag(Ae)V)^T K, G_s with Ee (16 r x 32 p) --
    float accz[4][4], accs[4][4];
    #pragma unroll
    for (int ni = 0; ni < 4; ni++)
        #pragma unroll
        for (int q = 0; q < 4; q++) { accz[ni][q] = 0.f; accs[ni][q] = 0.f; }
    #pragma unroll
    for (int p = 0; p < 8; p++) {
        int k0 = p * 8;
        float v00 = sv[(k0+t4)*65   + wm*16+gid];
        float v01 = sv[(k0+t4)*65   + wm*16+gid+8];
        float v10 = sv[(k0+t4+4)*65 + wm*16+gid];
        float v11 = sv[(k0+t4+4)*65 + wm*16+gid+8];
        float wz0 = sAe[k0+t4], wz1 = sAe[k0+t4+4];
        float ws0 = sEe[k0+t4], ws1 = sEe[k0+t4+4];
        unsigned az[4], as4[4];
        az[0]  = f2tf(v00*wz0); az[1]  = f2tf(v01*wz0);
        az[2]  = f2tf(v10*wz1); az[3]  = f2tf(v11*wz1);
        as4[0] = f2tf(v00*ws0); as4[1] = f2tf(v01*ws0);
        as4[2] = f2tf(v10*ws1); as4[3] = f2tf(v11*ws1);
        #pragma unroll
        for (int ni = 0; ni < 4; ni++) {
            int p0 = wn*32 + ni*8;
            unsigned bb[2];
            bb[0] = f2tf(sk[(k0+t4)*65   + p0+gid]);
            bb[1] = f2tf(sk[(k0+t4+4)*65 + p0+gid]);
            mma_tf32(accz[ni], az, bb);
            mma_tf32(accs[ni], as4, bb);
        }
    }
    #pragma unroll
    for (int ni = 0; ni < 4; ni++) {
        int r0 = wm*16 + gid;
        int p0 = wn*32 + ni*8 + 2*t4;
        size_t go = (size_t)cc*4096 + r0*64 + p0;
        *(float2*)(g_gz + go)      = make_float2(accz[ni][0], accz[ni][1]);
        *(float2*)(g_gz + go+512)  = make_float2(accz[ni][2], accz[ni][3]);  // (r0+8)*64
        *(float2*)(g_gs + go)      = make_float2(accs[ni][0], accs[ni][1]);
        *(float2*)(g_gs + go+512)  = make_float2(accs[ni][2], accs[ni][3]);
    }
    if (tid < 128) g_sc[(size_t)cc*128 + tid] = ssc[tid];
    if (tid >= 128 && tid < 131) g_sc2[(size_t)cc*4 + (tid-128)] = ssc2[tid-128];
}

// ---------------- 4b. chunk kernel B: sequential carries, prefetched ------
__global__ __launch_bounds__(256, 1)
void k_chunkB() {
    __shared__ float sQ[64*65];
    __shared__ float sS[16*65], sZ[16*65];
    __shared__ float ssc[128];
    __shared__ float ssc2[4];
    int tid = threadIdx.x;
    int bh = blockIdx.x >> 2, rb_ = blockIdx.x & 3;
    int b = bh >> 3, h = bh & 7;
    int rg = rb_ * 16;
    const size_t base = (size_t)b * Nn * DIi + h * DHh;
    int lane = tid & 31, wid = tid >> 5;
    int wm = wid & 3, wn = wid >> 2;
    int g = lane >> 2, t4 = lane & 3;
    int f4 = tid & 15, r0q = tid >> 4;
    int cidx = tid * 4;
    int crow = cidx >> 6, ccol = cidx & 63;

    for (int i = tid; i < 16*65; i += 256) { sS[i] = 0.f; sZ[i] = 0.f; }

    float4 rq[4];
    #pragma unroll
    for (int rr = 0; rr < 4; rr++)
        rq[rr] = *(const float4*)(g_qp + base + (size_t)(rr*16 + r0q)*DIi + f4*4);
    float rsc  = (tid < 128) ? g_sc[(size_t)(bh*16)*128 + tid] : 0.f;
    float rsc2 = (tid < 4)   ? g_sc2[(size_t)(bh*16)*4 + tid] : 0.f;
    __syncthreads();

    for (int c = 0; c < NC; c++) {
        int cc = bh*16 + c, t0 = c * CS;
        #pragma unroll
        for (int rr = 0; rr < 4; rr++) {
            int so = (rr*16 + r0q)*65 + f4*4;
            sQ[so]=rq[rr].x; sQ[so+1]=rq[rr].y; sQ[so+2]=rq[rr].z; sQ[so+3]=rq[rr].w;
        }
        if (tid < 128) ssc[tid] = rsc;
        if (tid < 4)   ssc2[tid] = rsc2;
        __syncthreads();

        size_t go = (size_t)cc*4096 + (rg+crow)*64 + ccol;
        float4 rgz = *(const float4*)(g_gz + go);
        float4 rgs = *(const float4*)(g_gs + go);
        if (c + 1 < NC) {
            int tn = t0 + CS;
            #pragma unroll
            for (int rr = 0; rr < 4; rr++)
                rq[rr] = *(const float4*)(g_qp + base + (size_t)(tn + rr*16 + r0q)*DIi + f4*4);
            if (tid < 128) rsc  = g_sc[(size_t)(cc+1)*128 + tid];
            if (tid < 4)   rsc2 = g_sc2[(size_t)(cc+1)*4 + tid];
        }

        float y1[4] = {0.f,0.f,0.f,0.f}, y2[4] = {0.f,0.f,0.f,0.f};
        #pragma unroll
        for (int k0 = 0; k0 < 64; k0 += 8) {
            unsigned a[4], bs[2], bz[2];
            a[0] = f2tf(sQ[(wm*16+g)*65   + k0+t4]);
            a[1] = f2tf(sQ[(wm*16+g+8)*65 + k0+t4]);
            a[2] = f2tf(sQ[(wm*16+g)*65   + k0+t4+4]);
            a[3] = f2tf(sQ[(wm*16+g+8)*65 + k0+t4+4]);
            bs[0] = f2tf(sS[(wn*8+g)*65 + k0+t4]);
            bs[1] = f2tf(sS[(wn*8+g)*65 + k0+t4+4]);
            bz[0] = f2tf(sZ[(wn*8+g)*65 + k0+t4]);
            bz[1] = f2tf(sZ[(wn*8+g)*65 + k0+t4+4]);
            mma_tf32(y1, a, bs);
            mma_tf32(y2, a, bz);
        }
        {
            int i0 = wm*16 + g;
            int rr = rg + wn*8 + 2*t4;
            float dm0 = ssc[i0*2],     f0 = ssc[i0*2+1];
            float dm1 = ssc[(i0+8)*2], f1 = ssc[(i0+8)*2+1];
            float* p0 = g_y + base + (size_t)(t0+i0)*DIi + rr;
            float* p1 = g_y + base + (size_t)(t0+i0+8)*DIi + rr;
            float2 e0 = *(float2*)p0, e1 = *(float2*)p1;
            e0.x += dm0*y1[0] - f0*y2[0]; e0.y += dm0*y1[1] - f0*y2[1];
            e1.x += dm1*y1[2] - f1*y2[2]; e1.y += dm1*y1[3] - f1*y2[3];
            *(float2*)p0 = e0; *(float2*)p1 = e1;
        }
        __syncthreads();
        {
            float ame = ssc2[0], dme = ssc2[1], fe = ssc2[2];
            float* ps = &sS[crow*65 + ccol];
            float* pz = &sZ[crow*65 + ccol];
            float s0=ps[0], s1=ps[1], s2=ps[2], s3=ps[3];
            float z0=pz[0], z1=pz[1], z2=pz[2], z3=pz[3];
            ps[0] = dme*s0 - fe*z0 + rgs.x; pz[0] = ame*z0 - rgz.x;
            ps[1] = dme*s1 - fe*z1 + rgs.y; pz[1] = ame*z1 - rgz.y;
            ps[2] = dme*s2 - fe*z2 + rgs.z; pz[2] = ame*z2 - rgz.z;
            ps[3] = dme*s3 - fe*z3 + rgs.w; pz[3] = ame*z3 - rgz.w;
        }
        __syncthreads();
    }
}

// ---------------- launch ----------------
extern "C" void kernel_launch(void* const* d_in, const int* in_sizes, int n_in,
                              void* d_out, int out_size) {
    const float* x      = (const float*)d_in[0];
    const float* w_rms  = (const float*)d_in[1];
    const float* wq     = (const float*)d_in[2];
    const float* wk     = (const float*)d_in[3];
    const float* wv     = (const float*)d_in[4];
    const float* wo     = (const float*)d_in[5];
    const float* conv_q = (const float*)d_in[6];
    const float* conv_k = (const float*)d_in[7];
    const float* conv_v = (const float*)d_in[8];
    const float* gamma_q= (const float*)d_in[9];
    const float* gamma_k= (const float*)d_in[10];
    const float* lr_w   = (const float*)d_in[11];
    const float* lr_b   = (const float*)d_in[12];
    const float* decay_w= (const float*)d_in[13];
    const float* decay_b= (const float*)d_in[14];
    const float* mom_w  = (const float*)d_in[15];
    const float* mom_b  = (const float*)d_in[16];
    float* out = (float*)d_out;

    float *p_qp, *p_kp, *p_vp, *p_qp2, *p_kp2, *p_vp2, *p_y, *p_ga;
    cudaGetSymbolAddress((void**)&p_qp, g_qp);
    cudaGetSymbolAddress((void**)&p_kp, g_kp);
    cudaGetSymbolAddress((void**)&p_vp, g_vp);
    cudaGetSymbolAddress((void**)&p_qp2, g_qp2);
    cudaGetSymbolAddress((void**)&p_kp2, g_kp2);
    cudaGetSymbolAddress((void**)&p_vp2, g_vp2);
    cudaGetSymbolAddress((void**)&p_y,  g_y);
    cudaGetSymbolAddress((void**)&p_ga, g_ga);

    int smG3 = 2*(2080 + 4*8*128) * (int)sizeof(unsigned);   // 49408
    int smG1 = 2*(2080 + 2*8*128) * (int)sizeof(unsigned);   // 33024
    int smA  = 17092 * (int)sizeof(float);
    cudaFuncSetAttribute(k_gemm3, cudaFuncAttributeMaxDynamicSharedMemorySize, smG3);
    cudaFuncSetAttribute(k_gemm1, cudaFuncAttributeMaxDynamicSharedMemorySize, smG1);
    cudaFuncSetAttribute(k_chunkA, cudaFuncAttributeMaxDynamicSharedMemorySize, smA);

    cudaMemsetAsync(p_ga, 0, (size_t)BN * 24 * sizeof(float));

    k_rmsnorm<<<BN, 256>>>(x, w_rms);
    dim3 gqkv(DIi/256, BN/128, 6);
    k_gemm3<<<gqkv, 256, smG3>>>(wq, wk, wv, conv_q, conv_k, conv_v,
                                 p_qp, p_kp, p_vp, p_qp2, p_kp2, p_vp2);
    dim3 ggate(BN/64, 8);
    k_gates2<<<ggate, 256>>>(lr_w, decay_w, mom_w);
    k_chunkA<<<256, 256, smA>>>(lr_b, decay_b, mom_b, gamma_q, gamma_k);
    k_chunkB<<<64, 256>>>();
    dim3 gout(DIMM/128, BN/128);
    k_gemm1<<<gout, 256, smG1>>>(p_y, wo, out, DIMM, DIi);
}

// round 12
// speedup vs baseline: 1.1551x; 1.1551x over previous
#include <cuda_runtime.h>
#include <math.h>

#define Bb   2
#define Nn   1024
#define DIMM 1024
#define Hh   8
#define DHh  64
#define DIi  512
#define BN   (Bb*Nn)
#define NC   16          // chunks per (b,h)
#define CS   64          // chunk size

static __device__ __constant__ float EPSf = 1.1920929e-07f;

// ---------------- scratch ----------------
__device__ float g_xa[BN*DIMM];
__device__ float g_qp[BN*DIi];
__device__ float g_kp[BN*DIi];
__device__ float g_vp[BN*DIi];
__device__ float g_y [BN*DIi];
__device__ float g_ga[BN*24];
__device__ float g_gz[256*4096];
__device__ float g_gs[256*4096];
__device__ float g_sc[256*128];
__device__ float g_sc2[256*4];

// ---------------- tf32 helpers ----------------
__device__ __forceinline__ unsigned f2tf(float f) {
    unsigned r; asm("cvt.rna.tf32.f32 %0, %1;" : "=r"(r) : "f"(f)); return r;
}
__device__ __forceinline__ uint4 tf4(float4 v) {
    return make_uint4(f2tf(v.x), f2tf(v.y), f2tf(v.z), f2tf(v.w));
}
__device__ __forceinline__ void mma_tf32(float* c, const unsigned* a, const unsigned* b) {
    asm volatile(
        "mma.sync.aligned.m16n8k8.row.col.f32.tf32.tf32.f32 "
        "{%0,%1,%2,%3}, {%4,%5,%6,%7}, {%8,%9}, {%0,%1,%2,%3};"
        : "+f"(c[0]), "+f"(c[1]), "+f"(c[2]), "+f"(c[3])
        : "r"(a[0]), "r"(a[1]), "r"(a[2]), "r"(a[3]), "r"(b[0]), "r"(b[1]));
}

// ---------------- 1. RMSNorm ----------------
__global__ void k_rmsnorm(const float* __restrict__ x, const float* __restrict__ w) {
    int row = blockIdx.x;
    int tid = threadIdx.x;
    const float4* xr = (const float4*)(x + (size_t)row * DIMM);
    float4 xv = xr[tid];
    float ss = xv.x*xv.x + xv.y*xv.y + xv.z*xv.z + xv.w*xv.w;
    #pragma unroll
    for (int o = 16; o > 0; o >>= 1) ss += __shfl_xor_sync(0xffffffffu, ss, o);
    __shared__ float sred[8];
    if ((tid & 31) == 0) sred[tid >> 5] = ss;
    __syncthreads();
    float tot = 0.f;
    #pragma unroll
    for (int i = 0; i < 8; i++) tot += sred[i];
    float inv = rsqrtf(tot * (1.0f / DIMM) + EPSf);
    float4 wv = ((const float4*)w)[tid];
    float4 o;
    o.x = xv.x * inv * wv.x; o.y = xv.y * inv * wv.y;
    o.z = xv.z * inv * wv.z; o.w = xv.w * inv * wv.w;
    ((float4*)g_xa)[(size_t)row * (DIMM/4) + tid] = o;
}

// ---------------- gates body (runs inside k_gemm3's shadow) ----------------
__device__ void gates_body(const float* __restrict__ lw, const float* __restrict__ dw,
                           const float* __restrict__ mw, int gb, void* smraw) {
    float* As = (float*)smraw;            // [64][20]
    float* Ws = (float*)smraw + 64*20;    // [16][24]
    int tid = threadIdx.x;
    int hh = tid & 7, ty = tid >> 3;
    int row0 = gb * 64;
    float acc[2][3] = {};
    for (int k0 = 0; k0 < DIMM; k0 += 16) {
        {
            int mm = tid >> 2, kq = (tid & 3) * 4;
            float4 v = *(const float4*)(g_xa + (size_t)(row0+mm)*DIMM + k0 + kq);
            As[mm*20+kq+0]=v.x; As[mm*20+kq+1]=v.y; As[mm*20+kq+2]=v.z; As[mm*20+kq+3]=v.w;
        }
        if (tid < 128) {
            int kk = tid >> 3, h2 = tid & 7;
            Ws[kk*24+h2]    = lw[(k0+kk)*Hh + h2];
            Ws[kk*24+8+h2]  = dw[(k0+kk)*Hh + h2];
            Ws[kk*24+16+h2] = mw[(k0+kk)*Hh + h2];
        }
        __syncthreads();
        #pragma unroll
        for (int kk = 0; kk < 16; kk++) {
            float a0 = As[(ty*2)*20+kk], a1 = As[(ty*2+1)*20+kk];
            float w0 = Ws[kk*24+hh], w1 = Ws[kk*24+8+hh], w2 = Ws[kk*24+16+hh];
            acc[0][0] += a0*w0; acc[0][1] += a0*w1; acc[0][2] += a0*w2;
            acc[1][0] += a1*w0; acc[1][1] += a1*w1; acc[1][2] += a1*w2;
        }
        __syncthreads();
    }
    #pragma unroll
    for (int i = 0; i < 2; i++) {
        int row = row0 + ty*2 + i;
        g_ga[row*24 + hh]      = acc[i][0];
        g_ga[row*24 + 8 + hh]  = acc[i][1];
        g_ga[row*24 + 16 + hh] = acc[i][2];
    }
}

// ---------------- 2. tf32 GEMM core: double-buffered smem -----------------
template<bool FC, int MI, int WCN>
__device__ __forceinline__ void gemm_tc(const float* __restrict__ A,
                                        const float* __restrict__ Bm,
                                        float* __restrict__ C,
                                        int Nc, int Kc,
                                        const float* __restrict__ cw) {
    extern __shared__ unsigned smem[];
    unsigned* As = smem;                  // [2][4*520]
    unsigned* Bs = smem + 2*2080;         // [2][WCN*8*128]
    const int BSW = WCN*8*128;
    int tid = threadIdx.x;
    int lane = tid & 31, wid = tid >> 5;
    int wr = wid / WCN, wc = wid % WCN;
    int gid = lane >> 2, tig = lane & 3;
    int row0 = blockIdx.y * 128, col0 = blockIdx.x * (WCN*64);

    int ar = tid >> 1;
    int kqb = (tid & 1) * 2;
    int bk = lane >> 1, bq = lane & 1;

    int m = row0 + ar;
    int tloc = 0, b0 = 0;
    if (FC) { b0 = m & ~(Nn - 1); tloc = m - b0; }

    float acc[MI][8][4];
    #pragma unroll
    for (int i = 0; i < MI; i++)
        #pragma unroll
        for (int j = 0; j < 8; j++)
            #pragma unroll
            for (int q = 0; q < 4; q++) acc[i][j][q] = 0.f;

    float4 ra[2], rb[WCN];
    const float4* A4 = (const float4*)A;
    const float4* B4 = (const float4*)Bm;
    const float4* XA4 = (const float4*)g_xa;
    const float4* CW4 = (const float4*)cw;

    #define PREFETCH(kn)                                                        \
    {                                                                           \
        _Pragma("unroll")                                                       \
        for (int p = 0; p < 2; p++) {                                           \
            int kq = kqb + p;                                                   \
            if (!FC) {                                                          \
                ra[p] = A4[(size_t)m * (Kc >> 2) + ((kn) >> 2) + kq];           \
            } else {                                                            \
                int kb = (kn) + kq * 4;                                         \
                float we[4][4];                                                 \
                _Pragma("unroll")                                               \
                for (int e = 0; e < 4; e++) *(float4*)we[e] = CW4[kb + e];      \
                float4 r = make_float4(0.f, 0.f, 0.f, 0.f);                     \
                _Pragma("unroll")                                               \
                for (int j = 0; j < 4; j++) {                                   \
                    int tl = tloc + j - 2;                                      \
                    if ((unsigned)tl < (unsigned)Nn) {                          \
                        float4 xv = XA4[(size_t)(b0 + tl) * (DIMM >> 2) + (kb >> 2)]; \
                        r.x += xv.x * we[0][j]; r.y += xv.y * we[1][j];         \
                        r.z += xv.z * we[2][j]; r.w += xv.w * we[3][j];         \
                    }                                                           \
                }                                                               \
                ra[p] = r;                                                      \
            }                                                                   \
        }                                                                       \
        _Pragma("unroll")                                                       \
        for (int p = 0; p < WCN; p++) {                                         \
            int nt = wid + p * 8;                                               \
            rb[p] = B4[(size_t)((kn) + bk) * (Nc >> 2) + (col0 >> 2) + nt * 2 + bq]; \
        }                                                                       \
    }

    #define STORE(buf)                                                          \
    {                                                                           \
        unsigned* Aw = As + (buf)*2080;                                         \
        unsigned* Bw = Bs + (buf)*BSW;                                          \
        _Pragma("unroll")                                                       \
        for (int p = 0; p < 2; p++)                                             \
            *(uint4*)&Aw[(kqb+p)*520 + ar*4] = tf4(ra[p]);                      \
        _Pragma("unroll")                                                       \
        for (int p = 0; p < WCN; p++) {                                         \
            int nt = wid + p * 8;                                               \
            *(uint4*)&Bw[nt*128 + bk*8 + bq*4] = tf4(rb[p]);                    \
        }                                                                       \
    }

    PREFETCH(0)
    STORE(0)
    __syncthreads();

    for (int k0 = 0; k0 < Kc; k0 += 16) {
        int cur = (k0 >> 4) & 1;
        bool more = (k0 + 16 < Kc);
        if (more) PREFETCH(k0 + 16)
        const unsigned* Abuf = As + cur*2080;
        const unsigned* Bbuf = Bs + cur*BSW;
        #pragma unroll
        for (int c = 0; c < 2; c++) {
            unsigned a[MI][4];
            const unsigned* s0 = Abuf + (c*2)*520;
            const unsigned* s1 = Abuf + (c*2+1)*520;
            #pragma unroll
            for (int mi = 0; mi < MI; mi++) {
                int m0 = (wr*MI + mi) * 16;
                a[mi][0] = s0[(m0+gid)*4 + tig];
                a[mi][1] = s0[(m0+gid+8)*4 + tig];
                a[mi][2] = s1[(m0+gid)*4 + tig];
                a[mi][3] = s1[(m0+gid+8)*4 + tig];
            }
            #pragma unroll
            for (int ni = 0; ni < 8; ni++) {
                int nt = wc*8 + ni;
                unsigned b[2];
                b[0] = Bbuf[nt*128 + (c*8+tig)*8 + gid];
                b[1] = Bbuf[nt*128 + (c*8+tig+4)*8 + gid];
                #pragma unroll
                for (int mi = 0; mi < MI; mi++) mma_tf32(acc[mi][ni], a[mi], b);
            }
        }
        if (more) {
            STORE(cur ^ 1)
            __syncthreads();
        }
    }
    #undef PREFETCH
    #undef STORE

    #pragma unroll
    for (int mi = 0; mi < MI; mi++) {
        #pragma unroll
        for (int ni = 0; ni < 8; ni++) {
            int row = row0 + (wr*MI + mi)*16 + gid;
            int col = col0 + (wc*8 + ni)*8 + tig*2;
            *(float2*)(C + (size_t)row * Nc + col) =
                make_float2(acc[mi][ni][0], acc[mi][ni][1]);
            *(float2*)(C + (size_t)(row+8) * Nc + col) =
                make_float2(acc[mi][ni][2], acc[mi][ni][3]);
        }
    }
}

// z<3: QKV GEMM tiles; z==3: gate projections (fills idle SMs of the wave)
__global__ __launch_bounds__(256, 1)
void k_gemm3(const float* __restrict__ B0, const float* __restrict__ B1,
             const float* __restrict__ B2,
             const float* __restrict__ cw0, const float* __restrict__ cw1,
             const float* __restrict__ cw2,
             const float* __restrict__ lw, const float* __restrict__ dw,
             const float* __restrict__ mw,
             float* __restrict__ C0, float* __restrict__ C1,
             float* __restrict__ C2) {
    if (blockIdx.z < 3) {
        const float* Bm = (blockIdx.z == 0) ? B0 : ((blockIdx.z == 1) ? B1 : B2);
        const float* cw = (blockIdx.z == 0) ? cw0 : ((blockIdx.z == 1) ? cw1 : cw2);
        float* C = (blockIdx.z == 0) ? C0 : ((blockIdx.z == 1) ? C1 : C2);
        gemm_tc<true, 4, 4>(nullptr, Bm, C, DIi, DIMM, cw);
    } else {
        extern __shared__ unsigned smraw[];
        int gb = blockIdx.y * 2 + blockIdx.x;   // 0..31
        gates_body(lw, dw, mw, gb, (void*)smraw);
    }
}

__global__ __launch_bounds__(256, 1)
void k_gemm1(const float* __restrict__ A, const float* __restrict__ Bm,
             float* __restrict__ C, int Nc, int Kc) {
    gemm_tc<false, 2, 2>(A, Bm, C, Nc, Kc, nullptr);
}

// ---------------- 4a. chunk kernel A (+ fused per-head RMSNorm) -----------
__global__ __launch_bounds__(256, 1)
void k_chunkA(const float* __restrict__ lb, const float* __restrict__ db,
              const float* __restrict__ mb,
              const float* __restrict__ gq, const float* __restrict__ gk) {
    extern __shared__ float sm[];
    float* sq  = sm;            // 64x65, reused as T
    float* sk  = sm + 4160;
    float* sv  = sm + 8320;
    float* sE  = sm + 12480;
    float* slr = sm + 16640;
    float* sde = sm + 16704;
    float* smo = sm + 16768;
    float* sAe = sm + 16832;
    float* sEe = sm + 16896;
    float* ssc = sm + 16960;
    float* ssc2= sm + 17088;

    int tid = threadIdx.x;
    int cc = blockIdx.x;
    int bh = cc >> 4, c = cc & 15;
    int b = bh >> 3, h = bh & 7;
    int t0 = c * CS;
    const size_t base = (size_t)b * Nn * DIi + h * DHh;

    // load q,k,v chunk into padded smem
    {
        int f4 = tid & 15, r0 = tid >> 4;
        #pragma unroll
        for (int rr = 0; rr < 4; rr++) {
            int row = rr*16 + r0;
            size_t g = base + (size_t)(t0+row)*DIi + f4*4;
            float4 vq = *(const float4*)(g_qp + g);
            float4 vk = *(const float4*)(g_kp + g);
            float4 vv = *(const float4*)(g_vp + g);
            int so = row*65 + f4*4;
            sq[so]=vq.x; sq[so+1]=vq.y; sq[so+2]=vq.z; sq[so+3]=vq.w;
            sk[so]=vk.x; sk[so+1]=vk.y; sk[so+2]=vk.z; sk[so+3]=vk.w;
            sv[so]=vv.x; sv[so+1]=vv.y; sv[so+2]=vv.z; sv[so+3]=vv.w;
        }
    }
    // gates (sigmoid)
    if (tid < 192) {
        int i = tid / 3, gi = tid - i*3;
        const float* bb = (gi==0) ? lb : ((gi==1) ? db : mb);
        float raw = g_ga[(size_t)(b*Nn + t0 + i)*24 + gi*8 + h] + bb[h];
        float v = 1.f/(1.f+__expf(-raw));
        ((gi==0) ? slr : ((gi==1) ? sde : smo))[i] = v;
    }
    __syncthreads();

    // fused per-head RMSNorm of q,k (4 threads per row); write q back for chunkB
    {
        int row = tid >> 2, seg = (tid & 3) * 16;
        float ssq = 0.f, ssk = 0.f;
        #pragma unroll
        for (int j = 0; j < 16; j++) {
            float a = sq[row*65 + seg + j]; ssq += a*a;
            float e = sk[row*65 + seg + j]; ssk += e*e;
        }
        ssq += __shfl_xor_sync(0xffffffffu, ssq, 1);
        ssq += __shfl_xor_sync(0xffffffffu, ssq, 2);
        ssk += __shfl_xor_sync(0xffffffffu, ssk, 1);
        ssk += __shfl_xor_sync(0xffffffffu, ssk, 2);
        float invq = 1.f / fmaxf(sqrtf(ssq) * 0.125f, 1e-8f);
        float invk = 1.f / fmaxf(sqrtf(ssk) * 0.125f, 1e-8f);
        float qb[16];
        #pragma unroll
        for (int j = 0; j < 16; j++) {
            float nq = sq[row*65 + seg + j] * invq * gq[h*DHh + seg + j];
            sq[row*65 + seg + j] = nq; qb[j] = nq;
            sk[row*65 + seg + j] = sk[row*65 + seg + j] * invk * gk[h*DHh + seg + j];
        }
        #pragma unroll
        for (int j = 0; j < 4; j++)
            *(float4*)(g_qp + base + (size_t)(t0+row)*DIi + seg + j*4) =
                make_float4(qb[j*4], qb[j*4+1], qb[j*4+2], qb[j*4+3]);
    }
    // coefficient recurrences (threads 0..63)
    if (tid < 64) {
        int u = tid;
        float A_=0.f, E_=0.f, Amul=1.f, Dmul=1.f, F=0.f;
        for (int i = 0; i < 64; i++) {
            sE[i*65 + u] = E_;
            if (u == i) { ssc[i*2] = Dmul; ssc[i*2+1] = F; }
            float ai = smo[i], di = sde[i], li = slr[i];
            A_ = ai * A_; if (u == i) A_ = 1.f;
            E_ = di * E_ + li * A_;
            Amul *= ai; F = di * F + li * Amul; Dmul *= di;
        }
        sAe[u] = A_; sEe[u] = E_;
        if (u == 0) { ssc2[0] = Amul; ssc2[1] = Dmul; ssc2[2] = F; }
    }
    __syncthreads();

    int tx = tid & 15, ty = tid >> 4;
    // GEMM1: attn[i][u] = q_i . k_u
    float a1[4][4];
    #pragma unroll
    for (int i = 0; i < 4; i++)
        #pragma unroll
        for (int j = 0; j < 4; j++) a1[i][j] = 0.f;
    for (int p = 0; p < 64; p++) {
        float aa[4], bb[4];
        #pragma unroll
        for (int j = 0; j < 4; j++) aa[j] = sq[(ty*4+j)*65 + p];
        #pragma unroll
        for (int j = 0; j < 4; j++) bb[j] = sk[(tx*4+j)*65 + p];
        #pragma unroll
        for (int i = 0; i < 4; i++)
            #pragma unroll
            for (int j = 0; j < 4; j++) a1[i][j] += aa[i]*bb[j];
    }
    __syncthreads();
    #pragma unroll
    for (int i = 0; i < 4; i++)
        #pragma unroll
        for (int j = 0; j < 4; j++)
            sq[(ty*4+i)*65 + tx*4+j] = a1[i][j] * sE[(ty*4+i)*65 + tx*4+j];
    __syncthreads();

    // GEMM2: y_intra -> g_y
    float a2[4][4];
    #pragma unroll
    for (int i = 0; i < 4; i++)
        #pragma unroll
        for (int j = 0; j < 4; j++) a2[i][j] = 0.f;
    for (int u = 0; u < 64; u++) {
        float aa[4], bb[4];
        #pragma unroll
        for (int j = 0; j < 4; j++) aa[j] = sq[(ty*4+j)*65 + u];
        #pragma unroll
        for (int j = 0; j < 4; j++) bb[j] = sv[u*65 + tx*4+j];
        #pragma unroll
        for (int i = 0; i < 4; i++)
            #pragma unroll
            for (int j = 0; j < 4; j++) a2[i][j] += aa[i]*bb[j];
    }
    #pragma unroll
    for (int i = 0; i < 4; i++)
        *(float4*)(g_y + base + (size_t)(t0 + ty*4+i)*DIi + tx*4) =
            make_float4(a2[i][0], a2[i][1], a2[i][2], a2[i][3]);

    // GEMM3/4: carry tiles
    float az[4][4], as_[4][4];
    #pragma unroll
    for (int i = 0; i < 4; i++)
        #pragma unroll
        for (int j = 0; j < 4; j++) { az[i][j]=0.f; as_[i][j]=0.f; }
    for (int u = 0; u < 64; u++) {
        float wz = sAe[u], ws = sEe[u];
        float aa[4], bb[4];
        #pragma unroll
        for (int j = 0; j < 4; j++) aa[j] = sv[u*65 + ty*4+j];
        #pragma unroll
        for (int j = 0; j < 4; j++) bb[j] = sk[u*65 + tx*4+j];
        #pragma unroll
        for (int i = 0; i < 4; i++) {
            float azw = wz*aa[i], asw = ws*aa[i];
            #pragma unroll
            for (int j = 0; j < 4; j++) { az[i][j] += azw*bb[j]; as_[i][j] += asw*bb[j]; }
        }
    }
    #pragma unroll
    for (int i = 0; i < 4; i++) {
        size_t go = (size_t)cc*4096 + (ty*4+i)*64 + tx*4;
        *(float4*)(g_gz + go) = make_float4(az[i][0], az[i][1], az[i][2], az[i][3]);
        *(float4*)(g_gs + go) = make_float4(as_[i][0], as_[i][1], as_[i][2], as_[i][3]);
    }
    if (tid < 128) g_sc[(size_t)cc*128 + tid] = ssc[tid];
    if (tid >= 128 && tid < 131) g_sc2[(size_t)cc*4 + (tid-128)] = ssc2[tid-128];
}

// ---------------- 4b. chunk kernel B: sequential carries, prefetched ------
__global__ __launch_bounds__(256, 1)
void k_chunkB() {
    __shared__ float sQ[64*65];
    __shared__ float sS[16*65], sZ[16*65];
    __shared__ float ssc[128];
    __shared__ float ssc2[4];
    int tid = threadIdx.x;
    int bh = blockIdx.x >> 2, rb_ = blockIdx.x & 3;
    int b = bh >> 3, h = bh & 7;
    int rg = rb_ * 16;
    const size_t base = (size_t)b * Nn * DIi + h * DHh;
    int lane = tid & 31, wid = tid >> 5;
    int wm = wid & 3, wn = wid >> 2;
    int g = lane >> 2, t4 = lane & 3;
    int f4 = tid & 15, r0q = tid >> 4;
    int cidx = tid * 4;
    int crow = cidx >> 6, ccol = cidx & 63;

    for (int i = tid; i < 16*65; i += 256) { sS[i] = 0.f; sZ[i] = 0.f; }

    float4 rq[4];
    #pragma unroll
    for (int rr = 0; rr < 4; rr++)
        rq[rr] = *(const float4*)(g_qp + base + (size_t)(rr*16 + r0q)*DIi + f4*4);
    float rsc  = (tid < 128) ? g_sc[(size_t)(bh*16)*128 + tid] : 0.f;
    float rsc2 = (tid < 4)   ? g_sc2[(size_t)(bh*16)*4 + tid] : 0.f;
    __syncthreads();

    for (int c = 0; c < NC; c++) {
        int cc = bh*16 + c, t0 = c * CS;
        #pragma unroll
        for (int rr = 0; rr < 4; rr++) {
            int so = (rr*16 + r0q)*65 + f4*4;
            sQ[so]=rq[rr].x; sQ[so+1]=rq[rr].y; sQ[so+2]=rq[rr].z; sQ[so+3]=rq[rr].w;
        }
        if (tid < 128) ssc[tid] = rsc;
        if (tid < 4)   ssc2[tid] = rsc2;
        __syncthreads();

        size_t go = (size_t)cc*4096 + (rg+crow)*64 + ccol;
        float4 rgz = *(const float4*)(g_gz + go);
        float4 rgs = *(const float4*)(g_gs + go);
        if (c + 1 < NC) {
            int tn = t0 + CS;
            #pragma unroll
            for (int rr = 0; rr < 4; rr++)
                rq[rr] = *(const float4*)(g_qp + base + (size_t)(tn + rr*16 + r0q)*DIi + f4*4);
            if (tid < 128) rsc  = g_sc[(size_t)(cc+1)*128 + tid];
            if (tid < 4)   rsc2 = g_sc2[(size_t)(cc+1)*4 + tid];
        }

        float y1[4] = {0.f,0.f,0.f,0.f}, y2[4] = {0.f,0.f,0.f,0.f};
        #pragma unroll
        for (int k0 = 0; k0 < 64; k0 += 8) {
            unsigned a[4], bs[2], bz[2];
            a[0] = f2tf(sQ[(wm*16+g)*65   + k0+t4]);
            a[1] = f2tf(sQ[(wm*16+g+8)*65 + k0+t4]);
            a[2] = f2tf(sQ[(wm*16+g)*65   + k0+t4+4]);
            a[3] = f2tf(sQ[(wm*16+g+8)*65 + k0+t4+4]);
            bs[0] = f2tf(sS[(wn*8+g)*65 + k0+t4]);
            bs[1] = f2tf(sS[(wn*8+g)*65 + k0+t4+4]);
            bz[0] = f2tf(sZ[(wn*8+g)*65 + k0+t4]);
            bz[1] = f2tf(sZ[(wn*8+g)*65 + k0+t4+4]);
            mma_tf32(y1, a, bs);
            mma_tf32(y2, a, bz);
        }
        {
            int i0 = wm*16 + g;
            int rr = rg + wn*8 + 2*t4;
            float dm0 = ssc[i0*2],     f0 = ssc[i0*2+1];
            float dm1 = ssc[(i0+8)*2], f1 = ssc[(i0+8)*2+1];
            float* p0 = g_y + base + (size_t)(t0+i0)*DIi + rr;
            float* p1 = g_y + base + (size_t)(t0+i0+8)*DIi + rr;
            float2 e0 = *(float2*)p0, e1 = *(float2*)p1;
            e0.x += dm0*y1[0] - f0*y2[0]; e0.y += dm0*y1[1] - f0*y2[1];
            e1.x += dm1*y1[2] - f1*y2[2]; e1.y += dm1*y1[3] - f1*y2[3];
            *(float2*)p0 = e0; *(float2*)p1 = e1;
        }
        __syncthreads();
        {
            float ame = ssc2[0], dme = ssc2[1], fe = ssc2[2];
            float* ps = &sS[crow*65 + ccol];
            float* pz = &sZ[crow*65 + ccol];
            float s0=ps[0], s1=ps[1], s2=ps[2], s3=ps[3];
            float z0=pz[0], z1=pz[1], z2=pz[2], z3=pz[3];
            ps[0] = dme*s0 - fe*z0 + rgs.x; pz[0] = ame*z0 - rgz.x;
            ps[1] = dme*s1 - fe*z1 + rgs.y; pz[1] = ame*z1 - rgz.y;
            ps[2] = dme*s2 - fe*z2 + rgs.z; pz[2] = ame*z2 - rgz.z;
            ps[3] = dme*s3 - fe*z3 + rgs.w; pz[3] = ame*z3 - rgz.w;
        }
        __syncthreads();
    }
}

// ---------------- launch ----------------
extern "C" void kernel_launch(void* const* d_in, const int* in_sizes, int n_in,
                              void* d_out, int out_size) {
    const float* x      = (const float*)d_in[0];
    const float* w_rms  = (const float*)d_in[1];
    const float* wq     = (const float*)d_in[2];
    const float* wk     = (const float*)d_in[3];
    const float* wv     = (const float*)d_in[4];
    const float* wo     = (const float*)d_in[5];
    const float* conv_q = (const float*)d_in[6];
    const float* conv_k = (const float*)d_in[7];
    const float* conv_v = (const float*)d_in[8];
    const float* gamma_q= (const float*)d_in[9];
    const float* gamma_k= (const float*)d_in[10];
    const float* lr_w   = (const float*)d_in[11];
    const float* lr_b   = (const float*)d_in[12];
    const float* decay_w= (const float*)d_in[13];
    const float* decay_b= (const float*)d_in[14];
    const float* mom_w  = (const float*)d_in[15];
    const float* mom_b  = (const float*)d_in[16];
    float* out = (float*)d_out;

    float *p_qp, *p_kp, *p_vp, *p_y;
    cudaGetSymbolAddress((void**)&p_qp, g_qp);
    cudaGetSymbolAddress((void**)&p_kp, g_kp);
    cudaGetSymbolAddress((void**)&p_vp, g_vp);
    cudaGetSymbolAddress((void**)&p_y,  g_y);

    int smG3 = 2*(2080 + 4*8*128) * (int)sizeof(unsigned);   // 49408
    int smG1 = 2*(2080 + 2*8*128) * (int)sizeof(unsigned);   // 33024
    int smA  = 17092 * (int)sizeof(float);
    cudaFuncSetAttribute(k_gemm3, cudaFuncAttributeMaxDynamicSharedMemorySize, smG3);
    cudaFuncSetAttribute(k_gemm1, cudaFuncAttributeMaxDynamicSharedMemorySize, smG1);
    cudaFuncSetAttribute(k_chunkA, cudaFuncAttributeMaxDynamicSharedMemorySize, smA);

    k_rmsnorm<<<BN, 256>>>(x, w_rms);
    dim3 gqkv(DIi/256, BN/128, 4);   // z<3: QKV GEMM, z==3: gates
    k_gemm3<<<gqkv, 256, smG3>>>(wq, wk, wv, conv_q, conv_k, conv_v,
                                 lr_w, decay_w, mom_w, p_qp, p_kp, p_vp);
    k_chunkA<<<256, 256, smA>>>(lr_b, decay_b, mom_b, gamma_q, gamma_k);
    k_chunkB<<<64, 256>>>();
    dim3 gout(DIMM/128, BN/128);
    k_gemm1<<<gout, 256, smG1>>>(p_y, wo, out, DIMM, DIi);
}